// round 4
// baseline (speedup 1.0000x reference)
#include <cuda_runtime.h>
#include <cuda_bf16.h>
#include <math_constants.h>

// GatingNetwork: out = softmax(mask_topk(x @ W^T + b, k=8), axis=-1)
// x: [N, D] f32, W: [E, D] f32, b: [E] f32, k: int32 scalar. out: [N, E] f32.
// N=16384, D=4096, E=128.
//
// Round 3: exact-fp32 products (reference is full-precision fp32), with
// TWO-LEVEL accumulation (64-term chunks folded into a running total) to cut
// accumulation-order error ~5x and avoid top-k boundary flips vs reference.

#define BM 128
#define BN 128
#define BK 16
#define TM 8
#define TN 8
#define NTHREADS 256
#define FOLD_EVERY 4   // fold chunk accumulator every 4 BK-iters = 64 K-terms

__device__ __forceinline__ float warpReduceMax(float v) {
    #pragma unroll
    for (int off = 16; off > 0; off >>= 1)
        v = fmaxf(v, __shfl_xor_sync(0xffffffffu, v, off));
    return v;
}

__device__ __forceinline__ float warpReduceSum(float v) {
    #pragma unroll
    for (int off = 16; off > 0; off >>= 1)
        v += __shfl_xor_sync(0xffffffffu, v, off);
    return v;
}

__global__ __launch_bounds__(NTHREADS, 1)
void gating_kernel(const float* __restrict__ x,
                   const float* __restrict__ W,
                   const float* __restrict__ bias,
                   const int* __restrict__ kptr,
                   float* __restrict__ out,
                   int N, int D, int E) {
    extern __shared__ float smem[];
    float* As = smem;              // BK*BM floats (k-major, transposed)
    float* Bs = smem + BK * BM;    // BK*BN floats
    // Epilogue reuses the whole smem region as logits[BM][BN] (64 KB)

    const int tid = threadIdx.x;
    const int tx = tid % 16;
    const int ty = tid / 16;
    const int m0 = blockIdx.x * BM;

    float accT[TM][TN];   // running total
    float accC[TM][TN];   // per-chunk accumulator
    #pragma unroll
    for (int i = 0; i < TM; i++)
        #pragma unroll
        for (int j = 0; j < TN; j++) { accT[i][j] = 0.0f; accC[i][j] = 0.0f; }

    const int nIters = D / BK;             // 256
    const int nBig = nIters / FOLD_EVERY;  // 64

    for (int big = 0; big < nBig; big++) {
        #pragma unroll 1
        for (int sub = 0; sub < FOLD_EVERY; sub++) {
            const int k0 = (big * FOLD_EVERY + sub) * BK;
            // ---- load A tile (x rows), store transposed As[k][row] ----
            #pragma unroll
            for (int u = 0; u < 2; u++) {
                int f = tid * 2 + u;              // 0..511
                int row = f >> 2;
                int kc4 = f & 3;
                float4 v = *reinterpret_cast<const float4*>(
                    &x[(size_t)(m0 + row) * D + k0 + kc4 * 4]);
                As[(kc4 * 4 + 0) * BM + row] = v.x;
                As[(kc4 * 4 + 1) * BM + row] = v.y;
                As[(kc4 * 4 + 2) * BM + row] = v.z;
                As[(kc4 * 4 + 3) * BM + row] = v.w;
            }
            // ---- load B tile (W rows = experts), store transposed ----
            #pragma unroll
            for (int u = 0; u < 2; u++) {
                int f = tid * 2 + u;
                int e = f >> 2;
                int kc4 = f & 3;
                float4 v = *reinterpret_cast<const float4*>(
                    &W[(size_t)e * D + k0 + kc4 * 4]);
                Bs[(kc4 * 4 + 0) * BN + e] = v.x;
                Bs[(kc4 * 4 + 1) * BN + e] = v.y;
                Bs[(kc4 * 4 + 2) * BN + e] = v.z;
                Bs[(kc4 * 4 + 3) * BN + e] = v.w;
            }
            __syncthreads();

            #pragma unroll
            for (int kk = 0; kk < BK; kk++) {
                float a[TM], bb[TN];
                float4 a0 = *reinterpret_cast<const float4*>(&As[kk * BM + ty * TM]);
                float4 a1 = *reinterpret_cast<const float4*>(&As[kk * BM + ty * TM + 4]);
                a[0]=a0.x; a[1]=a0.y; a[2]=a0.z; a[3]=a0.w;
                a[4]=a1.x; a[5]=a1.y; a[6]=a1.z; a[7]=a1.w;
                float4 b0 = *reinterpret_cast<const float4*>(&Bs[kk * BN + tx * TN]);
                float4 b1 = *reinterpret_cast<const float4*>(&Bs[kk * BN + tx * TN + 4]);
                bb[0]=b0.x; bb[1]=b0.y; bb[2]=b0.z; bb[3]=b0.w;
                bb[4]=b1.x; bb[5]=b1.y; bb[6]=b1.z; bb[7]=b1.w;
                #pragma unroll
                for (int i = 0; i < TM; i++)
                    #pragma unroll
                    for (int j = 0; j < TN; j++)
                        accC[i][j] = fmaf(a[i], bb[j], accC[i][j]);
            }
            __syncthreads();
        }
        // ---- fold chunk into total (shortens error random walk) ----
        #pragma unroll
        for (int i = 0; i < TM; i++)
            #pragma unroll
            for (int j = 0; j < TN; j++) {
                accT[i][j] += accC[i][j];
                accC[i][j] = 0.0f;
            }
    }

    // ---- epilogue: bias add, stage logits tile in smem ----
    float bv[TN];
    #pragma unroll
    for (int j = 0; j < TN; j++) bv[j] = bias[tx * TN + j];

    float* logits = smem;  // [BM][BN]
    #pragma unroll
    for (int i = 0; i < TM; i++) {
        float4 lo = make_float4(accT[i][0] + bv[0], accT[i][1] + bv[1],
                                accT[i][2] + bv[2], accT[i][3] + bv[3]);
        float4 hi = make_float4(accT[i][4] + bv[4], accT[i][5] + bv[5],
                                accT[i][6] + bv[6], accT[i][7] + bv[7]);
        int row = ty * TM + i;
        *reinterpret_cast<float4*>(&logits[row * BN + tx * TN])     = lo;
        *reinterpret_cast<float4*>(&logits[row * BN + tx * TN + 4]) = hi;
    }
    __syncthreads();

    // ---- per-row top-k threshold + masked softmax ----
    const int k = kptr[0];
    const int lane = tid & 31;
    const int warp = tid >> 5;

    for (int r = warp; r < BM; r += NTHREADS / 32) {
        float4 vv = *reinterpret_cast<const float4*>(&logits[r * BN + lane * 4]);
        float vals[4] = {vv.x, vv.y, vv.z, vv.w};
        bool removed[4] = {false, false, false, false};

        float rowMax = -CUDART_INF_F;
        float thr = -CUDART_INF_F;
        for (int itk = 0; itk < k; itk++) {
            float localMax = -CUDART_INF_F;
            #pragma unroll
            for (int j = 0; j < 4; j++)
                if (!removed[j]) localMax = fmaxf(localMax, vals[j]);
            float wmax = warpReduceMax(localMax);
            if (itk == 0) rowMax = wmax;
            thr = wmax;
            unsigned ball = __ballot_sync(0xffffffffu, localMax == wmax);
            int src = __ffs(ball) - 1;
            if (lane == src) {
                #pragma unroll
                for (int j = 0; j < 4; j++) {
                    if (!removed[j] && vals[j] == wmax) { removed[j] = true; break; }
                }
            }
        }

        float ex[4];
        float s = 0.0f;
        #pragma unroll
        for (int j = 0; j < 4; j++) {
            ex[j] = (vals[j] >= thr) ? expf(vals[j] - rowMax) : 0.0f;
            s += ex[j];
        }
        s = warpReduceSum(s);
        float inv = 1.0f / s;
        float4 o = make_float4(ex[0] * inv, ex[1] * inv, ex[2] * inv, ex[3] * inv);
        *reinterpret_cast<float4*>(&out[(size_t)(m0 + r) * E + lane * 4]) = o;
    }
}

extern "C" void kernel_launch(void* const* d_in, const int* in_sizes, int n_in,
                              void* d_out, int out_size) {
    const float* x  = (const float*)d_in[0];
    const float* W  = (const float*)d_in[1];
    const float* b  = (const float*)d_in[2];
    const int*   kp = (const int*)d_in[3];

    int E = in_sizes[2];                 // 128
    int D = in_sizes[1] / E;             // 4096
    int N = in_sizes[0] / D;             // 16384
    float* out = (float*)d_out;

    const int smemBytes = BM * BN * sizeof(float);  // 64 KB (epilogue view)
    static bool attrSet = false;
    if (!attrSet) {
        cudaFuncSetAttribute(gating_kernel,
                             cudaFuncAttributeMaxDynamicSharedMemorySize, smemBytes);
        attrSet = true;
    }

    dim3 grid(N / BM);
    gating_kernel<<<grid, NTHREADS, smemBytes>>>(x, W, b, kp, out, N, D, E);
}

// round 8
// speedup vs baseline: 1.8412x; 1.8412x over previous
#include <cuda_runtime.h>
#include <cuda_bf16.h>
#include <math_constants.h>
#include <cstdint>

// GatingNetwork: out = softmax(mask_topk(x @ W^T + b, k=8), axis=-1)
// x: [N=16384, D=4096] f32, W: [E=128, D] f32, b: [E] f32, k=8. out: [N, E] f32.
//
// Round 7: mma.sync.m16n8k8 tf32 with 3xTF32 decomposition AND two-level
// accumulation (fold chunk->total every 4 iters = 128 K-terms) to eliminate
// the top-k boundary flips seen in R6 (4.7e-3 = ~3 flips from single-chain
// accumulation noise). A/B staged via cp.async double buffers; A stored raw
// in smem, tf32 hi/lo split at fragment-load time.

#define NTHREADS 256
#define BM 128
#define BN 128
#define BK 32
#define LSTRIDE 132
#define ASTRIDE 36              // floats per A row in smem (conflict-free frags)

// Pre-split, fragment-ordered W: per iter 32KB (16KB hi + 16KB lo)
__device__ __align__(16) unsigned char g_Wfrag[128 * 32768];

// smem layout (bytes)
#define A_RAW0 0
#define A_RAW1 18432
#define B_BUF0 36864
#define B_BUF1 69632
#define SMEM_BYTES 102400

__device__ __forceinline__ float to_tf32(float v) {
    float r;
    asm("cvt.rna.tf32.f32 %0, %1;" : "=f"(r) : "f"(v));
    return r;
}
__device__ __forceinline__ uint32_t smem_u32(const void* p) {
    uint32_t a;
    asm("{ .reg .u64 t; cvta.to.shared.u64 t, %1; cvt.u32.u64 %0, t; }"
        : "=r"(a) : "l"(p));
    return a;
}

#define CP_ASYNC16(dst, src) \
    asm volatile("cp.async.cg.shared.global [%0], [%1], 16;" \
                 :: "r"(dst), "l"(src) : "memory")
#define CP_COMMIT() asm volatile("cp.async.commit_group;" ::: "memory")
#define CP_WAIT1()  asm volatile("cp.async.wait_group 1;" ::: "memory")
#define CP_WAIT0()  asm volatile("cp.async.wait_group 0;" ::: "memory")

#define MMA_TF32(c, a, b) \
    asm volatile("mma.sync.aligned.m16n8k8.row.col.f32.tf32.tf32.f32 " \
        "{%0,%1,%2,%3}, {%4,%5,%6,%7}, {%8,%9}, {%0,%1,%2,%3};" \
        : "+f"((c)[0]), "+f"((c)[1]), "+f"((c)[2]), "+f"((c)[3]) \
        : "r"((a)[0]), "r"((a)[1]), "r"((a)[2]), "r"((a)[3]), \
          "r"((b)[0]), "r"((b)[1]))

__device__ __forceinline__ float warpReduceMax(float v) {
    #pragma unroll
    for (int off = 16; off > 0; off >>= 1)
        v = fmaxf(v, __shfl_xor_sync(0xffffffffu, v, off));
    return v;
}
__device__ __forceinline__ float warpReduceSum(float v) {
    #pragma unroll
    for (int off = 16; off > 0; off >>= 1)
        v += __shfl_xor_sync(0xffffffffu, v, off);
    return v;
}

// ---------------- prep: split W to tf32 hi/lo in B-fragment order ----------------
// B fragment (m16n8k8.row.col): thread t holds b0 = B[k=t%4][n=t/4],
// b1 = B[k=t%4+4][n=t/4]. Tile (ks, nt) packed as 32 lanes x 8 bytes.
__global__ void prep_w_kernel(const float* __restrict__ W, int n4, int D) {
    int i = blockIdx.x * blockDim.x + threadIdx.x;
    if (i >= n4) return;
    int d4PerRow = D / 4;
    int e  = i / d4PerRow;
    int d0 = (i - e * d4PerRow) * 4;
    float4 v = reinterpret_cast<const float4*>(W)[i];
    float4 h, l;
    h.x = to_tf32(v.x); l.x = to_tf32(v.x - h.x);
    h.y = to_tf32(v.y); l.y = to_tf32(v.y - h.y);
    h.z = to_tf32(v.z); l.z = to_tf32(v.z - h.z);
    h.w = to_tf32(v.w); l.w = to_tf32(v.w - h.w);
    int it = d0 >> 5;
    int kk = d0 & 31;
    int ks = kk >> 3;
    int chalf = (kk & 7) >> 2;
    int nt = e >> 3;
    int lane0 = (e & 7) * 4;
    size_t base = (size_t)it * 32768;
    unsigned char* pH = g_Wfrag + base;
    unsigned char* pL = g_Wfrag + base + 16384;
    int o = ((ks * 16 + nt) * 32 + lane0) * 8 + chalf * 4;
    *reinterpret_cast<float*>(pH + o)      = h.x;
    *reinterpret_cast<float*>(pH + o + 8)  = h.y;
    *reinterpret_cast<float*>(pH + o + 16) = h.z;
    *reinterpret_cast<float*>(pH + o + 24) = h.w;
    *reinterpret_cast<float*>(pL + o)      = l.x;
    *reinterpret_cast<float*>(pL + o + 8)  = l.y;
    *reinterpret_cast<float*>(pL + o + 16) = l.z;
    *reinterpret_cast<float*>(pL + o + 24) = l.w;
}

// ---------------- main fused kernel ----------------
__global__ __launch_bounds__(NTHREADS, 1)
void gating_mma_kernel(const float* __restrict__ x,
                       const float* __restrict__ bias,
                       const int* __restrict__ kptr,
                       float* __restrict__ out,
                       int N, int D, int E) {
    extern __shared__ char smem[];
    const uint32_t sb = smem_u32(smem);
    const int tid = threadIdx.x;
    const int lane = tid & 31;
    const int wid = tid >> 5;
    const int warpM = wid & 1;      // 0..1  (64 rows each)
    const int warpN = wid >> 1;     // 0..3  (32 cols each)
    const int m0 = blockIdx.x * BM;

    float accT[4][4][4];   // running totals
    float accC[4][4][4];   // per-chunk accumulators
    #pragma unroll
    for (int mt = 0; mt < 4; mt++)
        #pragma unroll
        for (int nt = 0; nt < 4; nt++)
            #pragma unroll
            for (int q = 0; q < 4; q++) { accT[mt][nt][q] = 0.0f; accC[mt][nt][q] = 0.0f; }

    const int iters = D / BK;       // 128

    // this thread's 4 A-chunk slots (constant across iters)
    // f = tid + u*256 in 0..1023; row = f>>3 (0..127); c4 = f&7 (16B column)
    // A smem addr: row*144 + c4*16 (ASTRIDE=36 floats = 144 B)
    // B: 2048 16B chunks, idx = tid + u*256 (u=0..7), linear

    // ---- pre-loop: issue buffers for it=0 ----
    {
        const int k0 = 0;
        #pragma unroll
        for (int u = 0; u < 4; u++) {
            int f = tid + u * NTHREADS;
            int row = f >> 3, c4 = f & 7;
            uint32_t dst = sb + A_RAW0 + (uint32_t)(row * 144 + c4 * 16);
            const float* src = &x[(size_t)(m0 + row) * D + k0 + c4 * 4];
            CP_ASYNC16(dst, src);
        }
        #pragma unroll
        for (int u = 0; u < 8; u++) {
            int idx = tid + u * NTHREADS;
            uint32_t dst = sb + B_BUF0 + (uint32_t)(idx * 16);
            const unsigned char* src = g_Wfrag + (size_t)idx * 16;
            CP_ASYNC16(dst, src);
        }
        CP_COMMIT();
    }

    for (int it = 0; it < iters; it++) {
        const int buf = it & 1;

        // ---- issue next iteration's copies into the other buffer ----
        if (it + 1 < iters) {
            const int k0 = (it + 1) * BK;
            const uint32_t aBase = sb + (buf ? A_RAW0 : A_RAW1);
            const uint32_t bBase = sb + (buf ? B_BUF0 : B_BUF1);
            #pragma unroll
            for (int u = 0; u < 4; u++) {
                int f = tid + u * NTHREADS;
                int row = f >> 3, c4 = f & 7;
                uint32_t dst = aBase + (uint32_t)(row * 144 + c4 * 16);
                const float* src = &x[(size_t)(m0 + row) * D + k0 + c4 * 4];
                CP_ASYNC16(dst, src);
            }
            const unsigned char* wsrc = g_Wfrag + (size_t)(it + 1) * 32768;
            #pragma unroll
            for (int u = 0; u < 8; u++) {
                int idx = tid + u * NTHREADS;
                uint32_t dst = bBase + (uint32_t)(idx * 16);
                CP_ASYNC16(dst, wsrc + (size_t)idx * 16);
            }
            CP_COMMIT();
            CP_WAIT1();        // current iter's group done; next may be in flight
        } else {
            CP_WAIT0();
        }
        __syncthreads();

        // ---- mma phase: A raw -> on-the-fly tf32 hi/lo split ----
        const float* aRaw = reinterpret_cast<const float*>(
            smem + (buf ? A_RAW1 : A_RAW0));
        const char* bB = smem + (buf ? B_BUF1 : B_BUF0);

        #pragma unroll
        for (int ks = 0; ks < 4; ks++) {
            uint32_t bh[4][2], bl[4][2];
            #pragma unroll
            for (int nt = 0; nt < 4; nt++) {
                int ob = ((ks * 16 + warpN * 4 + nt) * 32 + lane) * 8;
                uint2 vh = *reinterpret_cast<const uint2*>(bB + ob);
                uint2 vl = *reinterpret_cast<const uint2*>(bB + 16384 + ob);
                bh[nt][0] = vh.x; bh[nt][1] = vh.y;
                bl[nt][0] = vl.x; bl[nt][1] = vl.y;
            }
            #pragma unroll
            for (int mt = 0; mt < 4; mt++) {
                int r = (warpM * 4 + mt) * 16 + (lane >> 2);
                int i0 = r * ASTRIDE + ks * 8 + (lane & 3);
                float r0 = aRaw[i0];
                float r1 = aRaw[i0 + 8 * ASTRIDE];
                float r2 = aRaw[i0 + 4];
                float r3 = aRaw[i0 + 8 * ASTRIDE + 4];
                uint32_t ah[4], al[4];
                float h;
                h = to_tf32(r0); ah[0] = __float_as_uint(h); al[0] = __float_as_uint(to_tf32(r0 - h));
                h = to_tf32(r1); ah[1] = __float_as_uint(h); al[1] = __float_as_uint(to_tf32(r1 - h));
                h = to_tf32(r2); ah[2] = __float_as_uint(h); al[2] = __float_as_uint(to_tf32(r2 - h));
                h = to_tf32(r3); ah[3] = __float_as_uint(h); al[3] = __float_as_uint(to_tf32(r3 - h));
                #pragma unroll
                for (int nt = 0; nt < 4; nt++) {
                    MMA_TF32(accC[mt][nt], ah, bh[nt]);
                    MMA_TF32(accC[mt][nt], ah, bl[nt]);
                    MMA_TF32(accC[mt][nt], al, bh[nt]);
                }
            }
        }
        __syncthreads();

        // ---- two-level fold every 4 iters (128 K-terms per chunk) ----
        if ((it & 3) == 3) {
            #pragma unroll
            for (int mt = 0; mt < 4; mt++)
                #pragma unroll
                for (int nt = 0; nt < 4; nt++)
                    #pragma unroll
                    for (int q = 0; q < 4; q++) {
                        accT[mt][nt][q] += accC[mt][nt][q];
                        accC[mt][nt][q] = 0.0f;
                    }
        }
    }

    // ---- epilogue: fragments -> smem logits ----
    float* logits = reinterpret_cast<float*>(smem);
    #pragma unroll
    for (int mt = 0; mt < 4; mt++)
        #pragma unroll
        for (int nt = 0; nt < 4; nt++) {
            int r0 = warpM * 64 + mt * 16 + (lane >> 2);
            int c0 = warpN * 32 + nt * 8 + (lane & 3) * 2;
            logits[r0 * LSTRIDE + c0]           = accT[mt][nt][0];
            logits[r0 * LSTRIDE + c0 + 1]       = accT[mt][nt][1];
            logits[(r0 + 8) * LSTRIDE + c0]     = accT[mt][nt][2];
            logits[(r0 + 8) * LSTRIDE + c0 + 1] = accT[mt][nt][3];
        }
    __syncthreads();

    // ---- per-row top-k threshold + masked softmax (proven R3 epilogue) ----
    const int k = kptr[0];
    float4 bb4 = *reinterpret_cast<const float4*>(&bias[lane * 4]);

    for (int r = wid; r < BM; r += NTHREADS / 32) {
        float4 vv = *reinterpret_cast<const float4*>(&logits[r * LSTRIDE + lane * 4]);
        float vals[4] = {vv.x + bb4.x, vv.y + bb4.y, vv.z + bb4.z, vv.w + bb4.w};
        bool removed[4] = {false, false, false, false};

        float rowMax = -CUDART_INF_F;
        float thr = -CUDART_INF_F;
        for (int itk = 0; itk < k; itk++) {
            float localMax = -CUDART_INF_F;
            #pragma unroll
            for (int j = 0; j < 4; j++)
                if (!removed[j]) localMax = fmaxf(localMax, vals[j]);
            float wmax = warpReduceMax(localMax);
            if (itk == 0) rowMax = wmax;
            thr = wmax;
            unsigned ball = __ballot_sync(0xffffffffu, localMax == wmax);
            int src = __ffs(ball) - 1;
            if (lane == src) {
                #pragma unroll
                for (int j = 0; j < 4; j++) {
                    if (!removed[j] && vals[j] == wmax) { removed[j] = true; break; }
                }
            }
        }

        float ex[4];
        float s = 0.0f;
        #pragma unroll
        for (int j = 0; j < 4; j++) {
            ex[j] = (vals[j] >= thr) ? expf(vals[j] - rowMax) : 0.0f;
            s += ex[j];
        }
        s = warpReduceSum(s);
        float inv = 1.0f / s;
        float4 o = make_float4(ex[0] * inv, ex[1] * inv, ex[2] * inv, ex[3] * inv);
        *reinterpret_cast<float4*>(&out[(size_t)(m0 + r) * E + lane * 4]) = o;
    }
}

extern "C" void kernel_launch(void* const* d_in, const int* in_sizes, int n_in,
                              void* d_out, int out_size) {
    const float* x  = (const float*)d_in[0];
    const float* W  = (const float*)d_in[1];
    const float* b  = (const float*)d_in[2];
    const int*   kp = (const int*)d_in[3];

    int E = in_sizes[2];                 // 128
    int D = in_sizes[1] / E;             // 4096
    int N = in_sizes[0] / D;             // 16384
    float* out = (float*)d_out;

    static bool attrSet = false;
    if (!attrSet) {
        cudaFuncSetAttribute(gating_mma_kernel,
                             cudaFuncAttributeMaxDynamicSharedMemorySize, SMEM_BYTES);
        attrSet = true;
    }

    int n4 = (E * D) / 4;
    prep_w_kernel<<<(n4 + 255) / 256, 256>>>(W, n4, D);

    dim3 grid(N / BM);
    gating_mma_kernel<<<grid, NTHREADS, SMEM_BYTES>>>(x, b, kp, out, N, D, E);
}